// round 1
// baseline (speedup 1.0000x reference)
#include <cuda_runtime.h>
#include <math.h>

// ---------------- problem constants ----------------
#define NVOX   60000
#define DIM    128
#define NLAYER 12
#define NYY    400
#define NXX    400
#define NPIX   (2*NYY*NXX)     // 320000 output pixels (B=2)

#define LN0  24000
#define LN1  36000
#define CAP0 25
#define CAP1 100
#define NW0  960
#define NW1  360

// ---------------- static scratch (no runtime allocation allowed) ----------------
__device__ float g_pos   [2][NVOX*DIM];        // pos embeds per shift
__device__ float g_feat  [NVOX*DIM];           // working features
__device__ float g_resid [NVOX*DIM];           // residual / ffn2-out scratch
__device__ float g_qkin  [LN1*DIM];            // gathered feat+pos (level-compact)
__device__ float g_vf    [LN1*DIM];            // gathered feat
__device__ float g_qk    [LN1*2*DIM];          // Q|K fused GEMM out
__device__ float g_v     [LN1*DIM];            // V
__device__ float g_ao    [LN1*DIM];            // attention out (pre out-proj)
__device__ float g_po    [LN1*DIM];            // after out-proj
__device__ float g_h     [NVOX*256];           // FFN hidden
__device__ float g_canvas[(size_t)NPIX*DIM];   // NHWC BEV ping
__device__ float g_bev   [(size_t)NPIX*DIM];   // NHWC BEV pong
__device__ float g_wt    [2*DIM*9*DIM];        // conv weights re-laid [i*128+oc][tap][ic]

// ---------------- positional embedding ----------------
// pos[n,c]: axis=c>>6, j2=c&63, j=j2>>1; v=(ciw[n,axis]-6)/10000^(j/32); even j2 -> sin, odd -> cos
__global__ void pos_kernel(const float* __restrict__ ciw0, const float* __restrict__ ciw1,
                           float* __restrict__ pos)
{
    int n = blockIdx.x, s = blockIdx.y, c = threadIdx.x;
    const float* ciw = s ? ciw1 : ciw0;
    int axis = c >> 6, j2 = c & 63, j = j2 >> 1;
    float freq = powf(10000.0f, (float)j * (1.0f/32.0f));
    float v = (ciw[n*2 + axis] - 6.0f) / freq;
    pos[(size_t)s*NVOX*DIM + (size_t)n*DIM + c] = (j2 & 1) ? cosf(v) : sinf(v);
}

// ---------------- gather / scatter (level-compact layout) ----------------
__global__ void gather_kernel(const float* __restrict__ feat, const float* __restrict__ pos,
                              const int* __restrict__ vx,
                              float* __restrict__ qkin, float* __restrict__ vf)
{
    int j = blockIdx.x, c = threadIdx.x;
    int vv = vx[j];
    float f = feat[(size_t)vv*DIM + c];
    vf  [(size_t)j*DIM + c] = f;
    qkin[(size_t)j*DIM + c] = f + pos[(size_t)vv*DIM + c];
}

__global__ void scatter_kernel(const float* __restrict__ feat, const float* __restrict__ po,
                               const int* __restrict__ vx, float* __restrict__ resid)
{
    int j = blockIdx.x, c = threadIdx.x;
    int vv = vx[j];
    resid[(size_t)vv*DIM + c] = feat[(size_t)vv*DIM + c] + po[(size_t)j*DIM + c];
}

// ---------------- SGEMM: C[M,N] = A[M,K] @ W[N,K]^T + bias, optional exact-GELU ----------------
// BM=BN=128, BK=16, 256 threads, 8x8 micro-tile. N % 128 == 0, K % 16 == 0 (guaranteed here).
template<int EPI>   // 0 = none, 1 = gelu(exact)
__global__ void sgemm_kernel(const float* __restrict__ A, const float* __restrict__ W,
                             const float* __restrict__ bias, float* __restrict__ C,
                             int M, int N, int K)
{
    __shared__ float As[16][128];
    __shared__ float Ws[16][128];
    int bm = blockIdx.y * 128;
    int bn = blockIdx.x * 128;
    int tid = threadIdx.x;
    int ty = tid >> 4, tx = tid & 15;
    float acc[8][8];
    #pragma unroll
    for (int i = 0; i < 8; i++)
        #pragma unroll
        for (int j = 0; j < 8; j++) acc[i][j] = 0.0f;

    for (int k0 = 0; k0 < K; k0 += 16) {
        #pragma unroll
        for (int l = 0; l < 2; l++) {
            int f = tid + l*256;
            int r = f >> 2;
            int c = (f & 3) << 2;
            float4 v = make_float4(0.f,0.f,0.f,0.f);
            int row = bm + r;
            if (row < M) v = *(const float4*)(A + (size_t)row*K + k0 + c);
            As[c+0][r] = v.x; As[c+1][r] = v.y; As[c+2][r] = v.z; As[c+3][r] = v.w;
        }
        #pragma unroll
        for (int l = 0; l < 2; l++) {
            int f = tid + l*256;
            int r = f >> 2;
            int c = (f & 3) << 2;
            float4 v = *(const float4*)(W + (size_t)(bn + r)*K + k0 + c);
            Ws[c+0][r] = v.x; Ws[c+1][r] = v.y; Ws[c+2][r] = v.z; Ws[c+3][r] = v.w;
        }
        __syncthreads();
        #pragma unroll
        for (int k = 0; k < 16; k++) {
            float a[8], b[8];
            #pragma unroll
            for (int i = 0; i < 8; i++) a[i] = As[k][ty*8+i];
            #pragma unroll
            for (int j = 0; j < 8; j++) b[j] = Ws[k][tx*8+j];
            #pragma unroll
            for (int i = 0; i < 8; i++)
                #pragma unroll
                for (int j = 0; j < 8; j++) acc[i][j] = fmaf(a[i], b[j], acc[i][j]);
        }
        __syncthreads();
    }

    for (int i = 0; i < 8; i++) {
        int row = bm + ty*8 + i;
        if (row >= M) break;
        #pragma unroll
        for (int j = 0; j < 8; j++) {
            int col = bn + tx*8 + j;
            float v = acc[i][j] + bias[col];
            if (EPI == 1) v = 0.5f * v * (1.0f + erff(v * 0.70710678118654752f));
            C[(size_t)row*N + col] = v;
        }
    }
}

// ---------------- window attention (full windows, uniform CAP tokens) ----------------
// grid (num_windows, 8 heads); QK layout [row][0:128]=Q,[128:256]=K; V,O [row][128]
__global__ void attn_kernel(const float* __restrict__ QK, const float* __restrict__ V,
                            float* __restrict__ O, int cap)
{
    extern __shared__ float sm[];
    float* Ks = sm;            // cap*16
    float* Vs = sm + cap*16;   // cap*16
    int w = blockIdx.x, h = blockIdx.y;
    int base = w * cap;
    for (int idx = threadIdx.x; idx < cap*16; idx += blockDim.x) {
        int j = idx >> 4, d = idx & 15;
        Ks[idx] = QK[(size_t)(base+j)*256 + 128 + h*16 + d];
        Vs[idx] = V [(size_t)(base+j)*128 + h*16 + d];
    }
    __syncthreads();
    int t = threadIdx.x;
    if (t >= cap) return;
    float q[16];
    #pragma unroll
    for (int d = 0; d < 16; d++) q[d] = QK[(size_t)(base+t)*256 + h*16 + d] * 0.25f;  // /sqrt(16)

    // pass 1: online logsumexp
    float mx = -1e30f, s = 0.0f;
    for (int j = 0; j < cap; j++) {
        float sc = 0.f;
        #pragma unroll
        for (int d = 0; d < 16; d++) sc = fmaf(q[d], Ks[j*16+d], sc);
        float m2 = fmaxf(mx, sc);
        s = s * __expf(mx - m2) + __expf(sc - m2);
        mx = m2;
    }
    float inv = 1.0f / s;
    // pass 2: weighted V accumulation
    float o[16];
    #pragma unroll
    for (int d = 0; d < 16; d++) o[d] = 0.f;
    for (int j = 0; j < cap; j++) {
        float sc = 0.f;
        #pragma unroll
        for (int d = 0; d < 16; d++) sc = fmaf(q[d], Ks[j*16+d], sc);
        float p = __expf(sc - mx);
        #pragma unroll
        for (int d = 0; d < 16; d++) o[d] = fmaf(p, Vs[j*16+d], o[d]);
    }
    #pragma unroll
    for (int d = 0; d < 16; d++) O[(size_t)(base+t)*128 + h*16 + d] = o[d] * inv;
}

// ---------------- residual + LayerNorm: out = LN(x (+ r)) * g + b ----------------
__global__ void add_ln_kernel(const float* x, const float* r,
                              const float* __restrict__ g, const float* __restrict__ b,
                              float* out, int n)
{
    int row = blockIdx.x * blockDim.y + threadIdx.y;
    if (row >= n) return;
    int lane = threadIdx.x;
    float4 xv = ((const float4*)(x + (size_t)row*DIM))[lane];
    if (r) {
        float4 rv = ((const float4*)(r + (size_t)row*DIM))[lane];
        xv.x += rv.x; xv.y += rv.y; xv.z += rv.z; xv.w += rv.w;
    }
    float sum = xv.x + xv.y + xv.z + xv.w;
    float sq  = xv.x*xv.x + xv.y*xv.y + xv.z*xv.z + xv.w*xv.w;
    #pragma unroll
    for (int o = 16; o; o >>= 1) {
        sum += __shfl_xor_sync(0xffffffffu, sum, o);
        sq  += __shfl_xor_sync(0xffffffffu, sq,  o);
    }
    float mu  = sum * (1.0f/128.0f);
    float var = sq  * (1.0f/128.0f) - mu*mu;
    float rstd = rsqrtf(var + 1e-5f);
    float4 gv = ((const float4*)g)[lane];
    float4 bv = ((const float4*)b)[lane];
    float4 ov;
    ov.x = (xv.x - mu)*rstd*gv.x + bv.x;
    ov.y = (xv.y - mu)*rstd*gv.y + bv.y;
    ov.z = (xv.z - mu)*rstd*gv.z + bv.z;
    ov.w = (xv.w - mu)*rstd*gv.w + bv.w;
    ((float4*)(out + (size_t)row*DIM))[lane] = ov;
}

// ---------------- BEV scatter / zero / weight relayout / conv / transpose ----------------
__global__ void zero_kernel(float4* __restrict__ p, int n4)
{
    int i = blockIdx.x*blockDim.x + threadIdx.x;
    if (i < n4) p[i] = make_float4(0.f,0.f,0.f,0.f);
}

__global__ void bev_scatter_kernel(const float* __restrict__ feat, const int* __restrict__ coors,
                                   float* __restrict__ canvas)
{
    int j = blockIdx.x, c = threadIdx.x;
    int b = coors[j*4], y = coors[j*4+2], x = coors[j*4+3];
    canvas[((size_t)((b*NYY + y)*NXX + x))*DIM + c] = feat[(size_t)j*DIM + c];
}

// conv_w [2][oc][ic][3][3] -> wt [(i*128+oc)][tap][ic]
__global__ void wt_kernel(const float* __restrict__ cw, float* __restrict__ wt)
{
    int t = blockIdx.x*blockDim.x + threadIdx.x;
    if (t >= 2*128*9*128) return;
    int ic  = t & 127;
    int tap = (t >> 7) % 9;
    int oci = t / (128*9);
    wt[((size_t)oci*9 + tap)*128 + ic] = cw[((size_t)oci*128 + ic)*9 + tap];
}

// Implicit-GEMM dilated conv (NHWC): out[p][oc] = BNReLU( sum_{tap,ic} in[nbr(p,tap)][ic] * wt[oc][tap][ic] )
// grid 2500 blocks x 256 threads; BM=128 pixels, BN=128 oc (all), 8x8 micro-tile.
__global__ void conv_kernel(const float* __restrict__ in, const float* __restrict__ wt,
                            const float* __restrict__ bg, const float* __restrict__ bb,
                            const float* __restrict__ bm, const float* __restrict__ bv,
                            float* __restrict__ out)
{
    __shared__ float As[16][128];
    __shared__ float Ws[16][128];
    __shared__ int sb[128], sy[128], sx[128];
    int tid = threadIdx.x;
    int pm0 = blockIdx.x * 128;
    if (tid < 128) {
        int p = pm0 + tid;
        int b = p / (NYY*NXX);
        int rem = p - b*(NYY*NXX);
        sb[tid] = b; sy[tid] = rem / NXX; sx[tid] = rem % NXX;
    }
    __syncthreads();
    int ty = tid >> 4, tx = tid & 15;
    float acc[8][8];
    #pragma unroll
    for (int i = 0; i < 8; i++)
        #pragma unroll
        for (int j = 0; j < 8; j++) acc[i][j] = 0.0f;

    for (int tap = 0; tap < 9; tap++) {
        int dy = (tap/3)*2 - 2, dx = (tap%3)*2 - 2;
        for (int kc = 0; kc < 128; kc += 16) {
            #pragma unroll
            for (int l = 0; l < 2; l++) {
                int f = tid + l*256;
                int r = f >> 2;
                int c = (f & 3) << 2;
                int yy = sy[r] + dy, xx = sx[r] + dx;
                float4 v = make_float4(0.f,0.f,0.f,0.f);
                if (yy >= 0 && yy < NYY && xx >= 0 && xx < NXX)
                    v = *(const float4*)(in + ((size_t)((sb[r]*NYY + yy)*NXX + xx))*DIM + kc + c);
                As[c+0][r] = v.x; As[c+1][r] = v.y; As[c+2][r] = v.z; As[c+3][r] = v.w;
            }
            #pragma unroll
            for (int l = 0; l < 2; l++) {
                int f = tid + l*256;
                int r = f >> 2;               // oc
                int c = (f & 3) << 2;
                float4 v = *(const float4*)(wt + (size_t)r*1152 + tap*128 + kc + c);
                Ws[c+0][r] = v.x; Ws[c+1][r] = v.y; Ws[c+2][r] = v.z; Ws[c+3][r] = v.w;
            }
            __syncthreads();
            #pragma unroll
            for (int k = 0; k < 16; k++) {
                float a[8], b[8];
                #pragma unroll
                for (int i = 0; i < 8; i++) a[i] = As[k][ty*8+i];
                #pragma unroll
                for (int j = 0; j < 8; j++) b[j] = Ws[k][tx*8+j];
                #pragma unroll
                for (int i = 0; i < 8; i++)
                    #pragma unroll
                    for (int j = 0; j < 8; j++) acc[i][j] = fmaf(a[i], b[j], acc[i][j]);
            }
            __syncthreads();
        }
    }
    #pragma unroll
    for (int j = 0; j < 8; j++) {
        int oc = tx*8 + j;
        float sc = bg[oc] * rsqrtf(bv[oc] + 1e-3f);
        float sh = bb[oc] - bm[oc]*sc;
        #pragma unroll
        for (int i = 0; i < 8; i++) {
            int p = pm0 + ty*8 + i;
            float v = acc[i][j]*sc + sh;
            out[(size_t)p*DIM + oc] = fmaxf(v, 0.0f);
        }
    }
}

__global__ void to_nchw_kernel(const float* __restrict__ in, float* __restrict__ out)
{
    int p = blockIdx.x, c = threadIdx.x;
    int b = p / (NYY*NXX);
    int rem = p - b*(NYY*NXX);
    out[((size_t)(b*DIM + c))*(NYY*NXX) + rem] = in[(size_t)p*DIM + c];
}

// ---------------- orchestration ----------------
extern "C" void kernel_launch(void* const* d_in, const int* in_sizes, int n_in,
                              void* d_out, int out_size)
{
    const float* vfeat = (const float*)d_in[0];
    const int*   coors = (const int*)  d_in[1];
    const float* ciw0  = (const float*)d_in[2];
    const float* ciw1  = (const float*)d_in[3];
    const int* vx[2][2] = {
        { (const int*)d_in[4],  (const int*)d_in[6]  },   // shift 0: lvl0, lvl1
        { (const int*)d_in[8],  (const int*)d_in[10] }    // shift 1
    };
    const float* ipw = (const float*)d_in[12];
    const float* ipb = (const float*)d_in[13];
    const float* ow_ = (const float*)d_in[14];
    const float* ob_ = (const float*)d_in[15];
    const float* l1w = (const float*)d_in[16];
    const float* l1b = (const float*)d_in[17];
    const float* l2w = (const float*)d_in[18];
    const float* l2b = (const float*)d_in[19];
    const float* g1  = (const float*)d_in[20];
    const float* b1  = (const float*)d_in[21];
    const float* g2  = (const float*)d_in[22];
    const float* b2  = (const float*)d_in[23];
    const float* cw  = (const float*)d_in[24];
    const float* bg  = (const float*)d_in[25];
    const float* bb  = (const float*)d_in[26];
    const float* bm  = (const float*)d_in[27];
    const float* bvv = (const float*)d_in[28];

    float *pos, *feat, *resid, *qkin, *vf, *qk, *vbuf, *ao, *po, *h, *canvas, *bev, *wt;
    cudaGetSymbolAddress((void**)&pos,    g_pos);
    cudaGetSymbolAddress((void**)&feat,   g_feat);
    cudaGetSymbolAddress((void**)&resid,  g_resid);
    cudaGetSymbolAddress((void**)&qkin,   g_qkin);
    cudaGetSymbolAddress((void**)&vf,     g_vf);
    cudaGetSymbolAddress((void**)&qk,     g_qk);
    cudaGetSymbolAddress((void**)&vbuf,   g_v);
    cudaGetSymbolAddress((void**)&ao,     g_ao);
    cudaGetSymbolAddress((void**)&po,     g_po);
    cudaGetSymbolAddress((void**)&h,      g_h);
    cudaGetSymbolAddress((void**)&canvas, g_canvas);
    cudaGetSymbolAddress((void**)&bev,    g_bev);
    cudaGetSymbolAddress((void**)&wt,     g_wt);

    // positional embeds (both shifts) + conv weight relayout (independent)
    pos_kernel<<<dim3(NVOX, 2), 128>>>(ciw0, ciw1, pos);
    wt_kernel<<<(2*128*9*128 + 255)/256, 256>>>(cw, wt);

    const float* cur = vfeat;   // layer-0 reads input directly
    for (int li = 0; li < NLAYER; li++) {
        int s = li & 1;
        const float* posS = pos + (size_t)s*NVOX*DIM;
        for (int lvl = 0; lvl < 2; lvl++) {
            const int* vxp = vx[s][lvl];
            int ln  = lvl ? LN1  : LN0;
            int cap = lvl ? CAP1 : CAP0;
            int nw  = lvl ? NW1  : NW0;
            int my  = (ln + 127) / 128;

            gather_kernel<<<ln, 128>>>(cur, posS, vxp, qkin, vf);
            // QK fused: W = ipw[li][0:256], bias ipb[li][0:256]
            sgemm_kernel<0><<<dim3(2, my), 256>>>(qkin, ipw + (size_t)li*384*128,
                                                  ipb + (size_t)li*384, qk, ln, 256, 128);
            // V: W = ipw[li][256:384]
            sgemm_kernel<0><<<dim3(1, my), 256>>>(vf, ipw + (size_t)li*384*128 + 256*128,
                                                  ipb + (size_t)li*384 + 256, vbuf, ln, 128, 128);
            attn_kernel<<<dim3(nw, 8), (cap <= 32 ? 32 : 128), cap*32*(int)sizeof(float)>>>(qk, vbuf, ao, cap);
            sgemm_kernel<0><<<dim3(1, my), 256>>>(ao, ow_ + (size_t)li*128*128,
                                                  ob_ + (size_t)li*128, po, ln, 128, 128);
            scatter_kernel<<<ln, 128>>>(cur, po, vxp, resid);
        }
        // feat = LN(resid)
        add_ln_kernel<<<(NVOX + 7)/8, dim3(32, 8)>>>(resid, nullptr,
                                                     g1 + (size_t)li*128, b1 + (size_t)li*128, feat, NVOX);
        // h = gelu(feat @ l1w^T + l1b)
        sgemm_kernel<1><<<dim3(2, (NVOX + 127)/128), 256>>>(feat, l1w + (size_t)li*256*128,
                                                            l1b + (size_t)li*256, h, NVOX, 256, 128);
        // resid = h @ l2w^T + l2b
        sgemm_kernel<0><<<dim3(1, (NVOX + 127)/128), 256>>>(h, l2w + (size_t)li*128*256,
                                                            l2b + (size_t)li*128, resid, NVOX, 128, 256);
        // feat = LN(feat + resid)
        add_ln_kernel<<<(NVOX + 7)/8, dim3(32, 8)>>>(feat, resid,
                                                     g2 + (size_t)li*128, b2 + (size_t)li*128, feat, NVOX);
        cur = feat;
    }

    // BEV: zero canvas, scatter, two dilated conv+BN+ReLU, transpose to NCHW
    int n4 = (int)((size_t)NPIX*DIM/4);
    zero_kernel<<<(n4 + 255)/256, 256>>>((float4*)canvas, n4);
    bev_scatter_kernel<<<NVOX, 128>>>(feat, coors, canvas);
    conv_kernel<<<NPIX/128, 256>>>(canvas, wt,             bg,       bb,       bm,       bvv,       bev);
    conv_kernel<<<NPIX/128, 256>>>(bev,    wt + 128*1152,  bg + 128, bb + 128, bm + 128, bvv + 128, canvas);
    to_nchw_kernel<<<NPIX, 128>>>(canvas, (float*)d_out);
}

// round 3
// speedup vs baseline: 2.2608x; 2.2608x over previous
#include <cuda_runtime.h>
#include <math.h>

// ---------------- problem constants ----------------
#define NVOX   60000
#define DIM    128
#define NLAYER 12
#define NYY    400
#define NXX    400
#define NPIX   (2*NYY*NXX)

#define LN0  24000
#define LN1  36000
#define CAP0 25
#define CAP1 100
#define NW0  960
#define NW1  360

// ---------------- static scratch ----------------
__device__ float g_pos   [2][NVOX*DIM];
__device__ float g_feat  [NVOX*DIM];
__device__ float g_resid [NVOX*DIM];
__device__ float g_qkin  [LN1*DIM];
__device__ float g_vf    [LN1*DIM];
__device__ float g_qk    [LN1*2*DIM];
__device__ float g_v     [LN1*DIM];
__device__ float g_ao    [LN1*DIM];
__device__ float g_po    [LN1*DIM];
__device__ float g_h     [NVOX*256];
__device__ float g_canvas[(size_t)NPIX*DIM];
__device__ float g_bev   [(size_t)NPIX*DIM];
__device__ float g_wt    [2*DIM*9*DIM];

// ---------------- tf32 helpers ----------------
__device__ __forceinline__ unsigned f2tf(float x) {
    unsigned u;
    asm("cvt.rna.tf32.f32 %0, %1;" : "=r"(u) : "f"(x));
    return u;
}
__device__ __forceinline__ void mma8(float* d, const unsigned* a, const unsigned* b) {
    asm volatile(
        "mma.sync.aligned.m16n8k8.row.col.f32.tf32.tf32.f32 "
        "{%0,%1,%2,%3}, {%4,%5,%6,%7}, {%8,%9}, {%0,%1,%2,%3};"
        : "+f"(d[0]), "+f"(d[1]), "+f"(d[2]), "+f"(d[3])
        : "r"(a[0]), "r"(a[1]), "r"(a[2]), "r"(a[3]), "r"(b[0]), "r"(b[1]));
}

// ---------------- positional embedding ----------------
__global__ void pos_kernel(const float* __restrict__ ciw0, const float* __restrict__ ciw1,
                           float* __restrict__ pos)
{
    int n = blockIdx.x, s = blockIdx.y, c = threadIdx.x;
    const float* ciw = s ? ciw1 : ciw0;
    int axis = c >> 6, j2 = c & 63, j = j2 >> 1;
    float freq = powf(10000.0f, (float)j * (1.0f/32.0f));
    float v = (ciw[n*2 + axis] - 6.0f) / freq;
    pos[(size_t)s*NVOX*DIM + (size_t)n*DIM + c] = (j2 & 1) ? cosf(v) : sinf(v);
}

// ---------------- gather / scatter ----------------
__global__ void gather_kernel(const float* __restrict__ feat, const float* __restrict__ pos,
                              const int* __restrict__ vx,
                              float* __restrict__ qkin, float* __restrict__ vf)
{
    int j = blockIdx.x, c = threadIdx.x;
    int vv = vx[j];
    float f = feat[(size_t)vv*DIM + c];
    vf  [(size_t)j*DIM + c] = f;
    qkin[(size_t)j*DIM + c] = f + pos[(size_t)vv*DIM + c];
}

__global__ void scatter_kernel(const float* __restrict__ feat, const float* __restrict__ po,
                               const int* __restrict__ vx, float* __restrict__ resid)
{
    int j = blockIdx.x, c = threadIdx.x;
    int vv = vx[j];
    resid[(size_t)vv*DIM + c] = feat[(size_t)vv*DIM + c] + po[(size_t)j*DIM + c];
}

// ---------------- TF32 tensor-core GEMM ----------------
// C[M,N] = A[M,K] @ W[N,K]^T + bias, optional exact-GELU.
// 256 threads, BM=BN=128, BK=32. 8 warps in 4(m) x 2(n) grid, 32x64 per warp.
// Smem rows padded to 36 words -> conflict-free fragment loads.
template<int EPI>
__global__ void __launch_bounds__(256, 2)
gemm_tc(const float* __restrict__ A, const float* __restrict__ W,
        const float* __restrict__ bias, float* __restrict__ C,
        int M, int N, int K)
{
    __shared__ unsigned As[128][36];
    __shared__ unsigned Ws[128][36];
    int tid = threadIdx.x;
    int lane = tid & 31, warp = tid >> 5;
    int g = lane >> 2, tig = lane & 3;
    int wm = warp & 3, wn = warp >> 2;
    int bm = blockIdx.y * 128, bn = blockIdx.x * 128;

    float acc[2][8][4];
    #pragma unroll
    for (int i = 0; i < 2; i++)
        #pragma unroll
        for (int j = 0; j < 8; j++)
            #pragma unroll
            for (int q = 0; q < 4; q++) acc[i][j][q] = 0.0f;

    for (int k0 = 0; k0 < K; k0 += 32) {
        float4 av[4], wv[4];
        #pragma unroll
        for (int l = 0; l < 4; l++) {
            int f = tid + l*256;
            int r = f >> 3, c8 = (f & 7) << 2;
            int row = bm + r;
            av[l] = (row < M) ? *(const float4*)(A + (size_t)row*K + k0 + c8)
                              : make_float4(0.f,0.f,0.f,0.f);
            wv[l] = *(const float4*)(W + (size_t)(bn + r)*K + k0 + c8);
        }
        __syncthreads();
        #pragma unroll
        for (int l = 0; l < 4; l++) {
            int f = tid + l*256;
            int r = f >> 3, c8 = (f & 7) << 2;
            As[r][c8+0] = f2tf(av[l].x); As[r][c8+1] = f2tf(av[l].y);
            As[r][c8+2] = f2tf(av[l].z); As[r][c8+3] = f2tf(av[l].w);
            Ws[r][c8+0] = f2tf(wv[l].x); Ws[r][c8+1] = f2tf(wv[l].y);
            Ws[r][c8+2] = f2tf(wv[l].z); Ws[r][c8+3] = f2tf(wv[l].w);
        }
        __syncthreads();
        #pragma unroll
        for (int kk = 0; kk < 4; kk++) {
            unsigned a[2][4], b[8][2];
            #pragma unroll
            for (int tm = 0; tm < 2; tm++) {
                int rr = wm*32 + tm*16 + g;
                a[tm][0] = As[rr    ][kk*8 + tig];
                a[tm][1] = As[rr + 8][kk*8 + tig];
                a[tm][2] = As[rr    ][kk*8 + tig + 4];
                a[tm][3] = As[rr + 8][kk*8 + tig + 4];
            }
            #pragma unroll
            for (int tn = 0; tn < 8; tn++) {
                int cc = wn*64 + tn*8 + g;
                b[tn][0] = Ws[cc][kk*8 + tig];
                b[tn][1] = Ws[cc][kk*8 + tig + 4];
            }
            #pragma unroll
            for (int tm = 0; tm < 2; tm++)
                #pragma unroll
                for (int tn = 0; tn < 8; tn++)
                    mma8(acc[tm][tn], a[tm], b[tn]);
        }
        __syncthreads();
    }

    #pragma unroll
    for (int tm = 0; tm < 2; tm++) {
        int row0 = bm + wm*32 + tm*16 + g;
        #pragma unroll
        for (int tn = 0; tn < 8; tn++) {
            int col = bn + wn*64 + tn*8 + 2*tig;
            float b0 = bias[col], b1 = bias[col+1];
            #pragma unroll
            for (int h = 0; h < 2; h++) {
                int row = row0 + h*8;
                if (row >= M) continue;
                float v0 = acc[tm][tn][2*h+0] + b0;
                float v1 = acc[tm][tn][2*h+1] + b1;
                if (EPI == 1) {
                    v0 = 0.5f * v0 * (1.0f + erff(v0 * 0.70710678118654752f));
                    v1 = 0.5f * v1 * (1.0f + erff(v1 * 0.70710678118654752f));
                }
                *(float2*)(C + (size_t)row*N + col) = make_float2(v0, v1);
            }
        }
    }
}

// ---------------- TF32 implicit-GEMM dilated conv + BN(eval) + ReLU ----------------
__global__ void __launch_bounds__(256, 2)
conv_tc(const float* __restrict__ in, const float* __restrict__ wt,
        const float* __restrict__ bg, const float* __restrict__ bb,
        const float* __restrict__ bm_, const float* __restrict__ bv,
        float* __restrict__ out)
{
    __shared__ unsigned As[128][36];
    __shared__ unsigned Ws[128][36];
    __shared__ int sb[128], sy[128], sx[128];
    int tid = threadIdx.x;
    int lane = tid & 31, warp = tid >> 5;
    int g = lane >> 2, tig = lane & 3;
    int wm = warp & 3, wn = warp >> 2;
    int pm0 = blockIdx.x * 128;

    if (tid < 128) {
        int p = pm0 + tid;
        int b = p / (NYY*NXX);
        int rem = p - b*(NYY*NXX);
        sb[tid] = b; sy[tid] = rem / NXX; sx[tid] = rem % NXX;
    }
    __syncthreads();

    float acc[2][8][4];
    #pragma unroll
    for (int i = 0; i < 2; i++)
        #pragma unroll
        for (int j = 0; j < 8; j++)
            #pragma unroll
            for (int q = 0; q < 4; q++) acc[i][j][q] = 0.0f;

    for (int tap = 0; tap < 9; tap++) {
        int dy = (tap/3)*2 - 2, dx = (tap%3)*2 - 2;
        for (int kc = 0; kc < 128; kc += 32) {
            float4 av[4], wv[4];
            #pragma unroll
            for (int l = 0; l < 4; l++) {
                int f = tid + l*256;
                int r = f >> 3, c8 = (f & 7) << 2;
                int yy = sy[r] + dy, xx = sx[r] + dx;
                av[l] = make_float4(0.f,0.f,0.f,0.f);
                if (yy >= 0 && yy < NYY && xx >= 0 && xx < NXX)
                    av[l] = *(const float4*)(in + ((size_t)((sb[r]*NYY + yy)*NXX + xx))*DIM + kc + c8);
                wv[l] = *(const float4*)(wt + (size_t)r*1152 + tap*128 + kc + c8);
            }
            __syncthreads();
            #pragma unroll
            for (int l = 0; l < 4; l++) {
                int f = tid + l*256;
                int r = f >> 3, c8 = (f & 7) << 2;
                As[r][c8+0] = f2tf(av[l].x); As[r][c8+1] = f2tf(av[l].y);
                As[r][c8+2] = f2tf(av[l].z); As[r][c8+3] = f2tf(av[l].w);
                Ws[r][c8+0] = f2tf(wv[l].x); Ws[r][c8+1] = f2tf(wv[l].y);
                Ws[r][c8+2] = f2tf(wv[l].z); Ws[r][c8+3] = f2tf(wv[l].w);
            }
            __syncthreads();
            #pragma unroll
            for (int kk = 0; kk < 4; kk++) {
                unsigned a[2][4], b[8][2];
                #pragma unroll
                for (int tm = 0; tm < 2; tm++) {
                    int rr = wm*32 + tm*16 + g;
                    a[tm][0] = As[rr    ][kk*8 + tig];
                    a[tm][1] = As[rr + 8][kk*8 + tig];
                    a[tm][2] = As[rr    ][kk*8 + tig + 4];
                    a[tm][3] = As[rr + 8][kk*8 + tig + 4];
                }
                #pragma unroll
                for (int tn = 0; tn < 8; tn++) {
                    int cc = wn*64 + tn*8 + g;
                    b[tn][0] = Ws[cc][kk*8 + tig];
                    b[tn][1] = Ws[cc][kk*8 + tig + 4];
                }
                #pragma unroll
                for (int tm = 0; tm < 2; tm++)
                    #pragma unroll
                    for (int tn = 0; tn < 8; tn++)
                        mma8(acc[tm][tn], a[tm], b[tn]);
            }
            __syncthreads();
        }
    }

    #pragma unroll
    for (int tm = 0; tm < 2; tm++) {
        int row0 = pm0 + wm*32 + tm*16 + g;
        #pragma unroll
        for (int tn = 0; tn < 8; tn++) {
            int oc = wn*64 + tn*8 + 2*tig;
            float s0 = bg[oc]   * rsqrtf(bv[oc]   + 1e-3f);
            float s1 = bg[oc+1] * rsqrtf(bv[oc+1] + 1e-3f);
            float h0 = bb[oc]   - bm_[oc]  *s0;
            float h1 = bb[oc+1] - bm_[oc+1]*s1;
            #pragma unroll
            for (int h = 0; h < 2; h++) {
                int row = row0 + h*8;
                float v0 = fmaxf(acc[tm][tn][2*h+0]*s0 + h0, 0.0f);
                float v1 = fmaxf(acc[tm][tn][2*h+1]*s1 + h1, 0.0f);
                *(float2*)(out + (size_t)row*DIM + oc) = make_float2(v0, v1);
            }
        }
    }
}

// ---------------- window attention ----------------
__global__ void attn_kernel(const float* __restrict__ QK, const float* __restrict__ V,
                            float* __restrict__ O, int cap)
{
    extern __shared__ float sm[];
    float* Ks = sm;
    float* Vs = sm + cap*16;
    int w = blockIdx.x, h = blockIdx.y;
    int base = w * cap;
    for (int idx = threadIdx.x; idx < cap*16; idx += blockDim.x) {
        int j = idx >> 4, d = idx & 15;
        Ks[idx] = QK[(size_t)(base+j)*256 + 128 + h*16 + d];
        Vs[idx] = V [(size_t)(base+j)*128 + h*16 + d];
    }
    __syncthreads();
    int t = threadIdx.x;
    if (t >= cap) return;
    float q[16];
    #pragma unroll
    for (int d = 0; d < 16; d++) q[d] = QK[(size_t)(base+t)*256 + h*16 + d] * 0.25f;

    float mx = -1e30f, s = 0.0f;
    for (int j = 0; j < cap; j++) {
        float sc = 0.f;
        #pragma unroll
        for (int d = 0; d < 16; d++) sc = fmaf(q[d], Ks[j*16+d], sc);
        float m2 = fmaxf(mx, sc);
        s = s * __expf(mx - m2) + __expf(sc - m2);
        mx = m2;
    }
    float inv = 1.0f / s;
    float o[16];
    #pragma unroll
    for (int d = 0; d < 16; d++) o[d] = 0.f;
    for (int j = 0; j < cap; j++) {
        float sc = 0.f;
        #pragma unroll
        for (int d = 0; d < 16; d++) sc = fmaf(q[d], Ks[j*16+d], sc);
        float p = __expf(sc - mx);
        #pragma unroll
        for (int d = 0; d < 16; d++) o[d] = fmaf(p, Vs[j*16+d], o[d]);
    }
    #pragma unroll
    for (int d = 0; d < 16; d++) O[(size_t)(base+t)*128 + h*16 + d] = o[d] * inv;
}

// ---------------- residual + LayerNorm ----------------
__global__ void add_ln_kernel(const float* x, const float* r,
                              const float* __restrict__ g, const float* __restrict__ b,
                              float* out, int n)
{
    int row = blockIdx.x * blockDim.y + threadIdx.y;
    if (row >= n) return;
    int lane = threadIdx.x;
    float4 xv = ((const float4*)(x + (size_t)row*DIM))[lane];
    if (r) {
        float4 rv = ((const float4*)(r + (size_t)row*DIM))[lane];
        xv.x += rv.x; xv.y += rv.y; xv.z += rv.z; xv.w += rv.w;
    }
    float sum = xv.x + xv.y + xv.z + xv.w;
    float sq  = xv.x*xv.x + xv.y*xv.y + xv.z*xv.z + xv.w*xv.w;
    #pragma unroll
    for (int o = 16; o; o >>= 1) {
        sum += __shfl_xor_sync(0xffffffffu, sum, o);
        sq  += __shfl_xor_sync(0xffffffffu, sq,  o);
    }
    float mu  = sum * (1.0f/128.0f);
    float var = sq  * (1.0f/128.0f) - mu*mu;
    float rstd = rsqrtf(var + 1e-5f);
    float4 gv = ((const float4*)g)[lane];
    float4 bv = ((const float4*)b)[lane];
    float4 ov;
    ov.x = (xv.x - mu)*rstd*gv.x + bv.x;
    ov.y = (xv.y - mu)*rstd*gv.y + bv.y;
    ov.z = (xv.z - mu)*rstd*gv.z + bv.z;
    ov.w = (xv.w - mu)*rstd*gv.w + bv.w;
    ((float4*)(out + (size_t)row*DIM))[lane] = ov;
}

// ---------------- BEV helpers ----------------
__global__ void zero_kernel(float4* __restrict__ p, int n4)
{
    int i = blockIdx.x*blockDim.x + threadIdx.x;
    if (i < n4) p[i] = make_float4(0.f,0.f,0.f,0.f);
}

__global__ void bev_scatter_kernel(const float* __restrict__ feat, const int* __restrict__ coors,
                                   float* __restrict__ canvas)
{
    int j = blockIdx.x, c = threadIdx.x;
    int b = coors[j*4], y = coors[j*4+2], x = coors[j*4+3];
    canvas[((size_t)((b*NYY + y)*NXX + x))*DIM + c] = feat[(size_t)j*DIM + c];
}

__global__ void wt_kernel(const float* __restrict__ cw, float* __restrict__ wt)
{
    int t = blockIdx.x*blockDim.x + threadIdx.x;
    if (t >= 2*128*9*128) return;
    int ic  = t & 127;
    int tap = (t >> 7) % 9;
    int oci = t / (128*9);
    wt[((size_t)oci*9 + tap)*128 + ic] = cw[((size_t)oci*128 + ic)*9 + tap];
}

__global__ void to_nchw_kernel(const float* __restrict__ in, float* __restrict__ out)
{
    int p = blockIdx.x, c = threadIdx.x;
    int b = p / (NYY*NXX);
    int rem = p - b*(NYY*NXX);
    out[((size_t)(b*DIM + c))*(NYY*NXX) + rem] = in[(size_t)p*DIM + c];
}

// ---------------- orchestration ----------------
extern "C" void kernel_launch(void* const* d_in, const int* in_sizes, int n_in,
                              void* d_out, int out_size)
{
    const float* vfeat = (const float*)d_in[0];
    const int*   coors = (const int*)  d_in[1];
    const float* ciw0  = (const float*)d_in[2];
    const float* ciw1  = (const float*)d_in[3];
    const int* vx[2][2] = {
        { (const int*)d_in[4],  (const int*)d_in[6]  },
        { (const int*)d_in[8],  (const int*)d_in[10] }
    };
    const float* ipw = (const float*)d_in[12];
    const float* ipb = (const float*)d_in[13];
    const float* ow_ = (const float*)d_in[14];
    const float* ob_ = (const float*)d_in[15];
    const float* l1w = (const float*)d_in[16];
    const float* l1b = (const float*)d_in[17];
    const float* l2w = (const float*)d_in[18];
    const float* l2b = (const float*)d_in[19];
    const float* g1  = (const float*)d_in[20];
    const float* b1  = (const float*)d_in[21];
    const float* g2  = (const float*)d_in[22];
    const float* b2  = (const float*)d_in[23];
    const float* cw  = (const float*)d_in[24];
    const float* bg  = (const float*)d_in[25];
    const float* bb  = (const float*)d_in[26];
    const float* bm  = (const float*)d_in[27];
    const float* bvv = (const float*)d_in[28];

    float *pos, *feat, *resid, *qkin, *vf, *qk, *vbuf, *ao, *po, *h, *canvas, *bev, *wt;
    cudaGetSymbolAddress((void**)&pos,    g_pos);
    cudaGetSymbolAddress((void**)&feat,   g_feat);
    cudaGetSymbolAddress((void**)&resid,  g_resid);
    cudaGetSymbolAddress((void**)&qkin,   g_qkin);
    cudaGetSymbolAddress((void**)&vf,     g_vf);
    cudaGetSymbolAddress((void**)&qk,     g_qk);
    cudaGetSymbolAddress((void**)&vbuf,   g_v);
    cudaGetSymbolAddress((void**)&ao,     g_ao);
    cudaGetSymbolAddress((void**)&po,     g_po);
    cudaGetSymbolAddress((void**)&h,      g_h);
    cudaGetSymbolAddress((void**)&canvas, g_canvas);
    cudaGetSymbolAddress((void**)&bev,    g_bev);
    cudaGetSymbolAddress((void**)&wt,     g_wt);

    pos_kernel<<<dim3(NVOX, 2), 128>>>(ciw0, ciw1, pos);
    wt_kernel<<<(2*128*9*128 + 255)/256, 256>>>(cw, wt);

    const float* cur = vfeat;
    for (int li = 0; li < NLAYER; li++) {
        int s = li & 1;
        const float* posS = pos + (size_t)s*NVOX*DIM;
        for (int lvl = 0; lvl < 2; lvl++) {
            const int* vxp = vx[s][lvl];
            int ln  = lvl ? LN1  : LN0;
            int cap = lvl ? CAP1 : CAP0;
            int nw  = lvl ? NW1  : NW0;
            int my  = (ln + 127) / 128;

            gather_kernel<<<ln, 128>>>(cur, posS, vxp, qkin, vf);
            gemm_tc<0><<<dim3(2, my), 256>>>(qkin, ipw + (size_t)li*384*128,
                                             ipb + (size_t)li*384, qk, ln, 256, 128);
            gemm_tc<0><<<dim3(1, my), 256>>>(vf, ipw + (size_t)li*384*128 + 256*128,
                                             ipb + (size_t)li*384 + 256, vbuf, ln, 128, 128);
            attn_kernel<<<dim3(nw, 8), (cap <= 32 ? 32 : 128), cap*32*(int)sizeof(float)>>>(qk, vbuf, ao, cap);
            gemm_tc<0><<<dim3(1, my), 256>>>(ao, ow_ + (size_t)li*128*128,
                                             ob_ + (size_t)li*128, po, ln, 128, 128);
            scatter_kernel<<<ln, 128>>>(cur, po, vxp, resid);
        }
        add_ln_kernel<<<(NVOX + 7)/8, dim3(32, 8)>>>(resid, nullptr,
                                                     g1 + (size_t)li*128, b1 + (size_t)li*128, feat, NVOX);
        gemm_tc<1><<<dim3(2, (NVOX + 127)/128), 256>>>(feat, l1w + (size_t)li*256*128,
                                                       l1b + (size_t)li*256, h, NVOX, 256, 128);
        gemm_tc<0><<<dim3(1, (NVOX + 127)/128), 256>>>(h, l2w + (size_t)li*128*256,
                                                       l2b + (size_t)li*128, resid, NVOX, 128, 256);
        add_ln_kernel<<<(NVOX + 7)/8, dim3(32, 8)>>>(feat, resid,
                                                     g2 + (size_t)li*128, b2 + (size_t)li*128, feat, NVOX);
        cur = feat;
    }

    int n4 = (int)((size_t)NPIX*DIM/4);
    zero_kernel<<<(n4 + 255)/256, 256>>>((float4*)canvas, n4);
    bev_scatter_kernel<<<NVOX, 128>>>(feat, coors, canvas);
    conv_tc<<<NPIX/128, 256>>>(canvas, wt,            bg,       bb,       bm,       bvv,       bev);
    conv_tc<<<NPIX/128, 256>>>(bev,    wt + 128*1152, bg + 128, bb + 128, bm + 128, bvv + 128, canvas);
    to_nchw_kernel<<<NPIX, 128>>>(canvas, (float*)d_out);
}